// round 1
// baseline (speedup 1.0000x reference)
#include <cuda_runtime.h>
#include <cstdint>
#include <math.h>

// ---------------- problem constants ----------------
#define BN    16
#define CC    256
#define HIDN  512
#define NGRP  8
#define CGg   64          // HID / GROUPS
#define HWN   3136
#define CU    64          // C/4 bottleneck
#define NTOT  (BN*HWN)    // 50176
#define LRc   0.01f
#define SPLITK 28
#define PBZ   7           // (HWN/16)/SPLITK = 196/28

// ---------------- device scratch (no allocs allowed) ----------------
__device__ float g_w1[HIDN*CC];
__device__ float g_gamma[HIDN];
__device__ float g_beta[HIDN];
__device__ float g_w2[CC*HIDN];

__device__ float g_h1 [(size_t)BN*HIDN*HWN];   // 25.7M
__device__ float g_g  [(size_t)BN*HIDN*HWN];
__device__ float g_dg [(size_t)BN*HIDN*HWN];   // dg -> dgn -> dh1 (in place)
__device__ float g_y  [(size_t)BN*CC*HWN];     // y (and final modification)
__device__ float g_drec[(size_t)BN*CC*HWN];
__device__ float g_dy [(size_t)BN*CC*HWN];
__device__ float g_pre [(size_t)BN*CU*HWN];
__device__ float g_dpre[(size_t)BN*CU*HWN];

__device__ float g_mu[BN*NGRP];
__device__ float g_rstd[BN*NGRP];
__device__ float g_part[BN*HIDN*2];            // per (b,o): sum(dgn), sum(dgn*hat)
__device__ float g_s1[BN*NGRP], g_s2[BN*NGRP];
__device__ float g_dgamma[HIDN], g_dbeta[HIDN];
__device__ float g_cm[CC], g_cA[CC], g_cB[CC];
__device__ float g_split[(size_t)SPLITK*HIDN*CC];
__device__ float g_dW1[HIDN*CC], g_dW2[CC*HIDN];
__device__ float g_maskf[2*NTOT];
__device__ float g_dscale[2];
__device__ float g_pooled[BN*CC];
__device__ float g_gate[BN];
__device__ int   g_flagF, g_flagW;

// ---------------- math helpers ----------------
__device__ __forceinline__ float geluf(float x){
    return 0.5f*x*(1.0f + erff(x*0.70710678118654752440f));
}
__device__ __forceinline__ float gelu_grad(float x){
    float cdf = 0.5f*(1.0f + erff(x*0.70710678118654752440f));
    float pdf = 0.3989422804014327f*expf(-0.5f*x*x);
    return cdf + x*pdf;
}
__device__ __forceinline__ void block_reduce2(float& a, float& b){
    __shared__ float sa[256], sb[256];
    int t = threadIdx.x;
    sa[t]=a; sb[t]=b; __syncthreads();
    for (int s=128; s>0; s>>=1){
        if (t<s){ sa[t]+=sa[t+s]; sb[t]+=sb[t+s]; }
        __syncthreads();
    }
    a=sa[0]; b=sb[0];
}

// ---------------- init / mask handling ----------------
__global__ void reset_copy(const float* __restrict__ w1, const float* __restrict__ gam,
                           const float* __restrict__ bet, const float* __restrict__ w2){
    int i = blockIdx.x*blockDim.x + threadIdx.x;
    if (i==0){ g_flagF=0; g_flagW=0; }
    if (i < HIDN*CC) g_w1[i] = w1[i];
    if (i < CC*HIDN) g_w2[i] = w2[i];
    if (i < HIDN){ g_gamma[i]=gam[i]; g_beta[i]=bet[i]; }
}

__global__ void mask_detect(const unsigned int* __restrict__ mw){
    // scan first 25088 words (safe under 1/4/... byte layouts)
    int f=0, wd=0;
    for (int i = blockIdx.x*blockDim.x + threadIdx.x; i < 25088; i += gridDim.x*blockDim.x){
        unsigned v = mw[i];
        if (v == 0x3F800000u) f = 1;
        else if (v != 0u && v != 1u) wd = 1;
    }
    if (f)  atomicOr(&g_flagF, 1);
    if (wd) atomicOr(&g_flagW, 1);
}

__global__ void mask_convert(const void* __restrict__ mp){
    int mode = g_flagW ? 2 : (g_flagF ? 1 : 0);
    int n = 2*NTOT;
    for (int i = blockIdx.x*blockDim.x + threadIdx.x; i < n; i += gridDim.x*blockDim.x){
        bool v;
        if (mode==0)      v = ((const int*)mp)[i] != 0;
        else if (mode==1) v = ((const float*)mp)[i] != 0.0f;
        else              v = ((const unsigned char*)mp)[i] != 0;
        g_maskf[i] = v ? 1.0f : 0.0f;
    }
}

__global__ void inv_scale_kernel(){
    int s = blockIdx.x;
    float cnt = 0.f, d = 0.f;
    for (int i = threadIdx.x; i < NTOT; i += 256) cnt += 1.0f - g_maskf[s*NTOT + i];
    block_reduce2(cnt, d);
    if (threadIdx.x==0) g_dscale[s] = 2.0f/(cnt*256.0f + 1e-8f);
}

// ---------------- generic batched GEMM: out[b,m,p] = sum_k W(m,k)*X[b,k,p] ----------------
// XOP: 0 none, 1 multiply X by mask[b,p], 2 gelu(X)
// EPI: 0 store, 1 +aux(feat), 2 drec=(acc-y)*(1-mask)*scal, 3 *gelu'(aux=pre),
//      4 dy = acc*mask - aux(drec) + cA[m] + cB[m]*(y - cm[m])
template<int XOP, int EPI, bool WT>
__global__ __launch_bounds__(256) void gemm_wx(
    const float* __restrict__ W, const float* __restrict__ X, float* __restrict__ out,
    int M, int K,
    const float* __restrict__ mask, const float* __restrict__ aux,
    const float* __restrict__ y, const float* __restrict__ scal)
{
    __shared__ float Ws[16][64];
    __shared__ float Xs[16][68];
    int b  = blockIdx.z;
    int m0 = blockIdx.y*64, p0 = blockIdx.x*64;
    const float* Xb = X + (size_t)b*K*HWN;
    int tid = threadIdx.x;
    int ty = tid>>4, tx = tid&15;
    float acc[4][4] = {};

    for (int k0=0; k0<K; k0+=16){
        if (!WT){
            int m = tid>>2, k4 = (tid&3)*4;
            float4 w = *(const float4*)(W + (size_t)(m0+m)*K + k0 + k4);
            Ws[k4+0][m]=w.x; Ws[k4+1][m]=w.y; Ws[k4+2][m]=w.z; Ws[k4+3][m]=w.w;
        } else {
            int kk = tid>>4, m4 = (tid&15)*4;
            float4 w = *(const float4*)(W + (size_t)(k0+kk)*M + m0 + m4);
            *(float4*)&Ws[kk][m4] = w;
        }
        {
            int kk = tid>>4, c4 = (tid&15)*4;
            float4 xv = *(const float4*)(Xb + (size_t)(k0+kk)*HWN + p0 + c4);
            if (XOP==1){
                const float* mr = mask + (size_t)b*HWN + p0 + c4;
                xv.x*=mr[0]; xv.y*=mr[1]; xv.z*=mr[2]; xv.w*=mr[3];
            } else if (XOP==2){
                xv.x=geluf(xv.x); xv.y=geluf(xv.y); xv.z=geluf(xv.z); xv.w=geluf(xv.w);
            }
            *(float4*)&Xs[kk][c4] = xv;
        }
        __syncthreads();
        #pragma unroll
        for (int kk=0; kk<16; kk++){
            float4 a  = *(const float4*)&Ws[kk][ty*4];
            float4 bb = *(const float4*)&Xs[kk][tx*4];
            float av[4]={a.x,a.y,a.z,a.w}, bv[4]={bb.x,bb.y,bb.z,bb.w};
            #pragma unroll
            for (int i=0;i<4;i++)
                #pragma unroll
                for (int j=0;j<4;j++) acc[i][j] += av[i]*bv[j];
        }
        __syncthreads();
    }

    #pragma unroll
    for (int i=0;i<4;i++){
        int m = m0 + ty*4 + i;
        size_t rowbase = ((size_t)b*M + m)*HWN;
        #pragma unroll
        for (int j=0;j<4;j++){
            int p = p0 + tx*4 + j;
            size_t idx = rowbase + p;
            float v = acc[i][j];
            if (EPI==1){
                v += aux[idx];
            } else if (EPI==2){
                float inv = 1.0f - mask[(size_t)b*HWN + p];
                v = (v - y[idx]) * inv * scal[0];
            } else if (EPI==3){
                v *= gelu_grad(aux[idx]);
            } else if (EPI==4){
                float mk = mask[(size_t)b*HWN + p];
                v = v*mk - aux[idx] + g_cA[m] + g_cB[m]*(y[idx] - g_cm[m]);
            }
            out[idx] = v;
        }
    }
}

// ---------------- NT GEMM for weight grads: part[z,m,n] += sum_{b,p in z} A[b,m,p]*B[b,n,p] ----------------
__global__ __launch_bounds__(256) void gemm_nt(
    const float* __restrict__ A, const float* __restrict__ Bm,
    float* __restrict__ part, int Ma, int Nb)
{
    __shared__ float As[16][68];
    __shared__ float Bs[16][68];
    int z  = blockIdx.z;
    int m0 = blockIdx.y*64, n0 = blockIdx.x*64;
    int tid = threadIdx.x;
    int ty = tid>>4, tx = tid&15;
    int r = tid>>2, p4 = (tid&3)*4;
    float acc[4][4] = {};

    for (int b=0; b<BN; b++){
        const float* Ab = A  + ((size_t)b*Ma + m0 + r)*HWN;
        const float* Bb = Bm + ((size_t)b*Nb + n0 + r)*HWN;
        for (int blk=0; blk<PBZ; blk++){
            int p0 = (blk*SPLITK + z)*16;
            float4 av = *(const float4*)(Ab + p0 + p4);
            float4 bv = *(const float4*)(Bb + p0 + p4);
            As[p4+0][r]=av.x; As[p4+1][r]=av.y; As[p4+2][r]=av.z; As[p4+3][r]=av.w;
            Bs[p4+0][r]=bv.x; Bs[p4+1][r]=bv.y; Bs[p4+2][r]=bv.z; Bs[p4+3][r]=bv.w;
            __syncthreads();
            #pragma unroll
            for (int pp=0; pp<16; pp++){
                float4 a  = *(const float4*)&As[pp][ty*4];
                float4 bb = *(const float4*)&Bs[pp][tx*4];
                float avv[4]={a.x,a.y,a.z,a.w}, bvv[4]={bb.x,bb.y,bb.z,bb.w};
                #pragma unroll
                for (int i=0;i<4;i++)
                    #pragma unroll
                    for (int j=0;j<4;j++) acc[i][j] += avv[i]*bvv[j];
            }
            __syncthreads();
        }
    }
    #pragma unroll
    for (int i=0;i<4;i++){
        int m = m0 + ty*4 + i;
        #pragma unroll
        for (int j=0;j<4;j++){
            int n = n0 + tx*4 + j;
            part[((size_t)z*Ma + m)*Nb + n] = acc[i][j];
        }
    }
}

__global__ void reduce_split(const float* __restrict__ part, float* __restrict__ out, int n){
    int i = blockIdx.x*blockDim.x + threadIdx.x;
    if (i < n){
        float s = 0.f;
        for (int z=0; z<SPLITK; z++) s += part[(size_t)z*n + i];
        out[i] = s;
    }
}

// ---------------- GroupNorm fwd stats ----------------
__global__ void gn_stats(const float* __restrict__ h1){
    int bg = blockIdx.x;                      // b*8 + g  (slab is contiguous)
    size_t base = (size_t)bg * CGg * HWN;
    const float4* p4 = (const float4*)(h1 + base);
    int n4 = CGg*HWN/4;
    float s=0.f, sq=0.f;
    for (int i=threadIdx.x; i<n4; i+=256){
        float4 v = p4[i];
        s  += v.x+v.y+v.z+v.w;
        sq += v.x*v.x + v.y*v.y + v.z*v.z + v.w*v.w;
    }
    block_reduce2(s, sq);
    if (threadIdx.x==0){
        float n = (float)(CGg*HWN);
        float mean = s/n;
        float var  = sq/n - mean*mean;
        g_mu[bg] = mean;
        g_rstd[bg] = rsqrtf(var + 1e-5f);
    }
}

// g = gelu(gn(h1))
__global__ void gelu_gn(const float* __restrict__ h1, float* __restrict__ g){
    size_t i4 = (size_t)blockIdx.x*blockDim.x + threadIdx.x;
    size_t i  = i4*4;
    int po = (int)(i / HWN);
    int o  = po % HIDN;
    int bg = (po / HIDN)*NGRP + o/CGg;
    float mu=g_mu[bg], rs=g_rstd[bg], ga=g_gamma[o], be=g_beta[o];
    float4 v = ((const float4*)h1)[i4];
    v.x = geluf((v.x-mu)*rs*ga + be);
    v.y = geluf((v.y-mu)*rs*ga + be);
    v.z = geluf((v.z-mu)*rs*ga + be);
    v.w = geluf((v.w-mu)*rs*ga + be);
    ((float4*)g)[i4] = v;
}

// per-channel consist stats
__global__ void chan_stats(const float* __restrict__ y, const float* __restrict__ rm,
                           const float* __restrict__ rv){
    int c = blockIdx.x;
    float s=0.f, sq=0.f;
    for (int b=0; b<BN; b++){
        const float4* row = (const float4*)(y + ((size_t)b*CC + c)*HWN);
        for (int i=threadIdx.x; i<HWN/4; i+=256){
            float4 v = row[i];
            s  += v.x+v.y+v.z+v.w;
            sq += v.x*v.x + v.y*v.y + v.z*v.z + v.w*v.w;
        }
    }
    block_reduce2(s, sq);
    if (threadIdx.x==0){
        float n = (float)NTOT;
        float cm = s/n;
        float cv = (sq - n*cm*cm)/(n - 1.0f);
        float rve = rv[c] + 1e-8f;
        g_cm[c] = cm;
        g_cA[c] = 0.1f*2.0f*(cm - rm[c])/(256.0f*n);
        g_cB[c] = 0.1f*4.0f*(cv/rve - 1.0f)/(rve*256.0f*(n - 1.0f));
    }
}

// dgn = dg * gelu'(gn_out); also per-(b,o) row sums
__global__ void dgn_kernel(const float* __restrict__ h1, float* __restrict__ dg){
    int o = blockIdx.x, b = blockIdx.y;
    int bg = b*NGRP + o/CGg;
    float mu=g_mu[bg], rs=g_rstd[bg], ga=g_gamma[o], be=g_beta[o];
    size_t base = ((size_t)b*HIDN + o)*HWN;
    const float4* h4 = (const float4*)(h1 + base);
    float4* d4 = (float4*)(dg + base);
    float r0=0.f, r1=0.f;
    for (int i=threadIdx.x; i<HWN/4; i+=256){
        float4 h = h4[i];
        float4 d = d4[i];
        float hat, gn, dd;
        hat=(h.x-mu)*rs; gn=hat*ga+be; dd=d.x*gelu_grad(gn); r0+=dd; r1+=dd*hat; d.x=dd;
        hat=(h.y-mu)*rs; gn=hat*ga+be; dd=d.y*gelu_grad(gn); r0+=dd; r1+=dd*hat; d.y=dd;
        hat=(h.z-mu)*rs; gn=hat*ga+be; dd=d.z*gelu_grad(gn); r0+=dd; r1+=dd*hat; d.z=dd;
        hat=(h.w-mu)*rs; gn=hat*ga+be; dd=d.w*gelu_grad(gn); r0+=dd; r1+=dd*hat; d.w=dd;
        d4[i] = d;
    }
    block_reduce2(r0, r1);
    if (threadIdx.x==0){
        g_part[(b*HIDN+o)*2+0] = r0;
        g_part[(b*HIDN+o)*2+1] = r1;
    }
}

__global__ void reduce_part(){
    int t = threadIdx.x;  // 512
    float db=0.f, dga=0.f;
    for (int b=0;b<BN;b++){
        db  += g_part[(b*HIDN+t)*2+0];
        dga += g_part[(b*HIDN+t)*2+1];
    }
    g_dbeta[t]=db; g_dgamma[t]=dga;
    if (t < BN*NGRP){
        int b=t/NGRP, g=t%NGRP;
        float s1=0.f, s2=0.f;
        for (int j=0;j<CGg;j++){
            int o=g*CGg+j;
            float ga=g_gamma[o];
            s1 += ga*g_part[(b*HIDN+o)*2+0];
            s2 += ga*g_part[(b*HIDN+o)*2+1];
        }
        float inv = 1.0f/(float)(CGg*HWN);
        g_s1[t]=s1*inv; g_s2[t]=s2*inv;
    }
}

// dh1 = rstd*(dgn*gamma - s1 - hat*s2)    (in-place over dgn)
__global__ void dh1_kernel(const float* __restrict__ h1, float* __restrict__ dg){
    size_t i4 = (size_t)blockIdx.x*blockDim.x + threadIdx.x;
    size_t i  = i4*4;
    int po = (int)(i / HWN);
    int o  = po % HIDN;
    int bg = (po / HIDN)*NGRP + o/CGg;
    float mu=g_mu[bg], rs=g_rstd[bg], ga=g_gamma[o];
    float s1=g_s1[bg], s2=g_s2[bg];
    float4 h = ((const float4*)h1)[i4];
    float4 d = ((float4*)dg)[i4];
    d.x = rs*(d.x*ga - s1 - (h.x-mu)*rs*s2);
    d.y = rs*(d.y*ga - s1 - (h.y-mu)*rs*s2);
    d.z = rs*(d.z*ga - s1 - (h.z-mu)*rs*s2);
    d.w = rs*(d.w*ga - s1 - (h.w-mu)*rs*s2);
    ((float4*)dg)[i4] = d;
}

__global__ void update_params(){
    int i = blockIdx.x*blockDim.x + threadIdx.x;
    if (i < HIDN*CC) g_w1[i] -= LRc*g_dW1[i];
    if (i < CC*HIDN) g_w2[i] -= LRc*g_dW2[i];
    if (i < HIDN){ g_gamma[i] -= LRc*g_dgamma[i]; g_beta[i] -= LRc*g_dbeta[i]; }
}

// ---------------- gate path (param-independent) ----------------
__global__ void pooled_kernel(const float* __restrict__ x){
    int c = blockIdx.x, b = blockIdx.y;
    const float4* row = (const float4*)(x + ((size_t)b*CC + c)*HWN);
    float s=0.f, d=0.f;
    for (int i=threadIdx.x; i<HWN/4; i+=256){
        float4 v = row[i];
        s += v.x+v.y+v.z+v.w;
    }
    block_reduce2(s, d);
    if (threadIdx.x==0) g_pooled[b*CC+c] = s/(float)HWN;
}

__global__ void gate_kernel(const float* __restrict__ gw1, const float* __restrict__ gb1,
                            const float* __restrict__ gw2, const float* __restrict__ gb2){
    __shared__ float gh[BN*CU];
    int t = threadIdx.x;  // 256
    for (int j=t; j<BN*CU; j+=256){
        int b=j/CU, u=j%CU;
        float s = gb1[u];
        const float* pr = &g_pooled[b*CC];
        const float* wr = &gw1[u*CC];
        for (int c=0;c<CC;c++) s += pr[c]*wr[c];
        gh[j] = geluf(s);
    }
    __syncthreads();
    if (t < BN){
        float s = gb2[0];
        for (int u=0;u<CU;u++) s += gh[t*CU+u]*gw2[u];
        g_gate[t] = 1.0f/(1.0f + expf(-s));
    }
}

__global__ void final_out(const float* __restrict__ x, const float* __restrict__ mod,
                          const float* __restrict__ rs, float* __restrict__ out){
    size_t i4 = (size_t)blockIdx.x*blockDim.x + threadIdx.x;
    if (i4 >= (size_t)BN*CC*HWN/4) return;
    int b = (int)(i4 / ((size_t)CC*HWN/4));
    float sc = rs[0]*g_gate[b];
    float4 xv = ((const float4*)x)[i4];
    float4 mv = ((const float4*)mod)[i4];
    xv.x += sc*mv.x; xv.y += sc*mv.y; xv.z += sc*mv.z; xv.w += sc*mv.w;
    ((float4*)out)[i4] = xv;
}

// ---------------- host orchestration ----------------
extern "C" void kernel_launch(void* const* d_in, const int* in_sizes, int n_in,
                              void* d_out, int out_size){
    const float* x        = (const float*)d_in[0];
    const float* conv1_w  = (const float*)d_in[1];
    const float* gn_gammaI= (const float*)d_in[2];
    const float* gn_betaI = (const float*)d_in[3];
    const float* conv2_w  = (const float*)d_in[4];
    const float* rw1      = (const float*)d_in[5];
    const float* rw2      = (const float*)d_in[6];
    const float* gw1      = (const float*)d_in[7];
    const float* gb1      = (const float*)d_in[8];
    const float* gw2      = (const float*)d_in[9];
    const float* gb2      = (const float*)d_in[10];
    const float* rscale   = (const float*)d_in[11];
    const float* rm       = (const float*)d_in[12];
    const float* rv       = (const float*)d_in[13];
    const void*  masks    = d_in[14];

    void* p;
    #define SYMF(sym) (cudaGetSymbolAddress(&p, sym), (float*)p)
    float* pw1    = SYMF(g_w1);
    float* pw2    = SYMF(g_w2);
    float* ph1    = SYMF(g_h1);
    float* pg     = SYMF(g_g);
    float* pdg    = SYMF(g_dg);
    float* py     = SYMF(g_y);
    float* pdrec  = SYMF(g_drec);
    float* pdy    = SYMF(g_dy);
    float* ppre   = SYMF(g_pre);
    float* pdpre  = SYMF(g_dpre);
    float* psplit = SYMF(g_split);
    float* pdW1   = SYMF(g_dW1);
    float* pdW2   = SYMF(g_dW2);
    float* pmaskf = SYMF(g_maskf);
    float* pdscale= SYMF(g_dscale);
    #undef SYMF

    // ---- init ----
    reset_copy<<<512,256>>>(conv1_w, gn_gammaI, gn_betaI, conv2_w);
    mask_detect<<<32,256>>>((const unsigned int*)masks);
    mask_convert<<<98,1024>>>(masks);
    inv_scale_kernel<<<2,256>>>();
    pooled_kernel<<<dim3(CC,BN),256>>>(x);
    gate_kernel<<<1,256>>>(gw1, gb1, gw2, gb2);

    // ---- 2 inner TTT steps ----
    for (int s=0; s<2; s++){
        const float* mk = pmaskf + (size_t)s*NTOT;
        const float* sc = pdscale + s;

        // forward
        gemm_wx<0,0,false><<<dim3(49,8,BN),256>>>(pw1, x,    ph1,  512,256, nullptr,nullptr,nullptr,nullptr);
        gn_stats<<<128,256>>>(ph1);
        gelu_gn<<<25088,256>>>(ph1, pg);
        gemm_wx<0,1,false><<<dim3(49,4,BN),256>>>(pw2, pg,   py,   256,512, nullptr, x,     nullptr,nullptr);   // y = m + feat
        gemm_wx<1,0,false><<<dim3(49,1,BN),256>>>(rw1, py,   ppre,  64,256, mk,      nullptr,nullptr,nullptr);  // pre = rw1 @ (y*mask)
        gemm_wx<2,2,false><<<dim3(49,4,BN),256>>>(rw2, ppre, pdrec,256, 64, mk,      nullptr, py,    sc);       // drec
        chan_stats<<<256,256>>>(py, rm, rv);

        // backward through surprise
        gemm_wx<0,3,true ><<<dim3(49,1,BN),256>>>(rw2, pdrec, pdpre, 64,256, nullptr, ppre,  nullptr,nullptr);  // dpre
        gemm_wx<0,4,true ><<<dim3(49,4,BN),256>>>(rw1, pdpre, pdy,  256, 64, mk,      pdrec, py,     nullptr);  // dy

        // backward through modifier
        gemm_wx<0,0,true ><<<dim3(49,8,BN),256>>>(pw2, pdy,  pdg,   512,256, nullptr,nullptr,nullptr,nullptr);  // dg
        dgn_kernel<<<dim3(HIDN,BN),256>>>(ph1, pdg);
        reduce_part<<<1,512>>>();
        dh1_kernel<<<25088,256>>>(ph1, pdg);

        gemm_nt<<<dim3(8,4,SPLITK),256>>>(pdy, pg, psplit, 256,512);    // dW2[c,o]
        reduce_split<<<512,256>>>(psplit, pdW2, HIDN*CC);
        gemm_nt<<<dim3(4,8,SPLITK),256>>>(pdg, x,  psplit, 512,256);    // dW1[o,c]
        reduce_split<<<512,256>>>(psplit, pdW1, HIDN*CC);

        update_params<<<512,256>>>();
    }

    // ---- final forward with updated params ----
    gemm_wx<0,0,false><<<dim3(49,8,BN),256>>>(pw1, x,  ph1, 512,256, nullptr,nullptr,nullptr,nullptr);
    gn_stats<<<128,256>>>(ph1);
    gelu_gn<<<25088,256>>>(ph1, pg);
    gemm_wx<0,0,false><<<dim3(49,4,BN),256>>>(pw2, pg, py,  256,512, nullptr,nullptr,nullptr,nullptr);  // modification

    final_out<<<12544,256>>>(x, py, rscale, (float*)d_out);
    (void)in_sizes; (void)n_in; (void)out_size;
}

// round 2
// speedup vs baseline: 2.1138x; 2.1138x over previous
#include <cuda_runtime.h>
#include <cuda_bf16.h>
#include <cstdint>
#include <math.h>

// ---------------- problem constants ----------------
#define BN    16
#define CC    256
#define HIDN  512
#define NGRP  8
#define CGg   64          // HID / GROUPS
#define HWN   3136
#define CU    64          // C/4 bottleneck
#define NTOT  (BN*HWN)    // 50176
#define LRc   0.01f
#define SPLITK 14
#define PBZ   7           // (HWN/32)/SPLITK = 98/14

// ---------------- device scratch (no allocs allowed) ----------------
__device__ float g_w1[HIDN*CC];
__device__ float g_gamma[HIDN];
__device__ float g_beta[HIDN];
__device__ float g_w2[CC*HIDN];

__device__ float g_h1 [(size_t)BN*HIDN*HWN];   // 25.7M
__device__ float g_dg [(size_t)BN*HIDN*HWN];   // dg -> dh1 (in place)
__device__ float g_y  [(size_t)BN*CC*HWN];     // y (and final modification)
__device__ float g_drec[(size_t)BN*CC*HWN];
__device__ float g_dy [(size_t)BN*CC*HWN];
__device__ float g_pre [(size_t)BN*CU*HWN];
__device__ float g_dpre[(size_t)BN*CU*HWN];

__device__ float g_mu[BN*NGRP];
__device__ float g_rstd[BN*NGRP];
__device__ float g_part[BN*HIDN*2];            // per (b,o): sum(dgn), sum(dgn*hat)
__device__ float g_s1[BN*NGRP], g_s2[BN*NGRP];
__device__ float g_dgamma[HIDN], g_dbeta[HIDN];
__device__ float g_cm[CC], g_cA[CC], g_cB[CC];
__device__ float g_split[(size_t)SPLITK*HIDN*CC];
__device__ float g_dW1[HIDN*CC], g_dW2[CC*HIDN];
__device__ float g_maskf[2*NTOT];
__device__ float g_dscale[2];
__device__ float g_pooled[BN*CC];
__device__ float g_gate[BN];
__device__ int   g_flagF, g_flagW;

// ---------------- math helpers ----------------
__device__ __forceinline__ float geluf(float x){
    return 0.5f*x*(1.0f + erff(x*0.70710678118654752440f));
}
__device__ __forceinline__ float gelu_grad(float x){
    float cdf = 0.5f*(1.0f + erff(x*0.70710678118654752440f));
    float pdf = 0.3989422804014327f*expf(-0.5f*x*x);
    return cdf + x*pdf;
}
__device__ __forceinline__ void block_reduce2(float& a, float& b){
    __shared__ float sa[256], sb[256];
    int t = threadIdx.x;
    sa[t]=a; sb[t]=b; __syncthreads();
    for (int s=128; s>0; s>>=1){
        if (t<s){ sa[t]+=sa[t+s]; sb[t]+=sb[t+s]; }
        __syncthreads();
    }
    a=sa[0]; b=sb[0];
}
__device__ __forceinline__ unsigned pack_bf2(float a, float b){
    __nv_bfloat162 p = __floats2bfloat162_rn(a, b);
    return *(unsigned*)&p;
}
__device__ __forceinline__ unsigned smem_u32(const void* p){
    return (unsigned)__cvta_generic_to_shared(p);
}

// ---------------- init / mask handling ----------------
__global__ void reset_copy(const float* __restrict__ w1, const float* __restrict__ gam,
                           const float* __restrict__ bet, const float* __restrict__ w2){
    int i = blockIdx.x*blockDim.x + threadIdx.x;
    if (i==0){ g_flagF=0; g_flagW=0; }
    if (i < HIDN*CC) g_w1[i] = w1[i];
    if (i < CC*HIDN) g_w2[i] = w2[i];
    if (i < HIDN){ g_gamma[i]=gam[i]; g_beta[i]=bet[i]; }
}

__global__ void mask_detect(const unsigned int* __restrict__ mw){
    int f=0, wd=0;
    for (int i = blockIdx.x*blockDim.x + threadIdx.x; i < 25088; i += gridDim.x*blockDim.x){
        unsigned v = mw[i];
        if (v == 0x3F800000u) f = 1;
        else if (v != 0u && v != 1u) wd = 1;
    }
    if (f)  atomicOr(&g_flagF, 1);
    if (wd) atomicOr(&g_flagW, 1);
}

__global__ void mask_convert(const void* __restrict__ mp){
    int mode = g_flagW ? 2 : (g_flagF ? 1 : 0);
    int n = 2*NTOT;
    for (int i = blockIdx.x*blockDim.x + threadIdx.x; i < n; i += gridDim.x*blockDim.x){
        bool v;
        if (mode==0)      v = ((const int*)mp)[i] != 0;
        else if (mode==1) v = ((const float*)mp)[i] != 0.0f;
        else              v = ((const unsigned char*)mp)[i] != 0;
        g_maskf[i] = v ? 1.0f : 0.0f;
    }
}

__global__ void inv_scale_kernel(){
    int s = blockIdx.x;
    float cnt = 0.f, d = 0.f;
    for (int i = threadIdx.x; i < NTOT; i += 256) cnt += 1.0f - g_maskf[s*NTOT + i];
    block_reduce2(cnt, d);
    if (threadIdx.x==0) g_dscale[s] = 2.0f/(cnt*256.0f + 1e-8f);
}

// ============================================================================
// bf16 tensor-core GEMM: out[b,m,p] = sum_k W(m,k)*X[b,k,p]
// XOP: 0 none, 1 X*=mask[b,p], 2 X=gelu(X), 3 X=gelu(GN(h1)) (per-channel k)
// EPI: 0 store, 1 +aux, 2 drec=(acc-y)*(1-mask)*scal, 3 *=gelu'(aux),
//      4 dy = acc*mask - aux + cA[m] + cB[m]*(y - cm[m])
// ============================================================================
template<int XOP, int EPI, bool WT>
__global__ __launch_bounds__(256) void gemm_bf16(
    const float* __restrict__ W, const float* __restrict__ X, float* __restrict__ out,
    int M, int K,
    const float* __restrict__ mask, const float* __restrict__ aux,
    const float* __restrict__ y, const float* __restrict__ scal)
{
    __shared__ __nv_bfloat16 Ws[64][40];
    __shared__ __nv_bfloat16 Xs[32][72];
    int b  = blockIdx.z;
    int m0 = blockIdx.y*64, p0 = blockIdx.x*64;
    const float* Xb = X + (size_t)b*K*HWN;
    int tid  = threadIdx.x;
    int lane = tid & 31, warp = tid >> 5;
    int wm = warp >> 2, wp = warp & 3;
    float acc[2][2][4] = {};

    for (int k0 = 0; k0 < K; k0 += 32){
        // ---- W tile -> Ws[m][k] ----
        if (!WT){
            int m = tid >> 2, c0 = (tid & 3)*4;
            const float* wr = W + (size_t)(m0+m)*K + k0;
            #pragma unroll
            for (int h=0; h<2; h++){
                float4 w = *(const float4*)(wr + c0 + h*16);
                *(unsigned*)&Ws[m][c0 + h*16]     = pack_bf2(w.x, w.y);
                *(unsigned*)&Ws[m][c0 + h*16 + 2] = pack_bf2(w.z, w.w);
            }
        } else {
            int kk = tid & 31, cg = tid >> 5;
            #pragma unroll
            for (int h=0; h<2; h++){
                int mb = (cg + h*8)*4;
                float4 w = *(const float4*)(W + (size_t)(k0+kk)*M + m0 + mb);
                Ws[mb+0][kk] = __float2bfloat16(w.x);
                Ws[mb+1][kk] = __float2bfloat16(w.y);
                Ws[mb+2][kk] = __float2bfloat16(w.z);
                Ws[mb+3][kk] = __float2bfloat16(w.w);
            }
        }
        // ---- X tile -> Xs[k][p] ----
        {
            int kk = tid >> 3, c0 = (tid & 7)*8;
            const float* xr = Xb + (size_t)(k0+kk)*HWN + p0 + c0;
            float4 v0 = *(const float4*)xr;
            float4 v1 = *(const float4*)(xr+4);
            float vv[8] = {v0.x,v0.y,v0.z,v0.w,v1.x,v1.y,v1.z,v1.w};
            if (XOP==1){
                const float* mr = mask + (size_t)b*HWN + p0 + c0;
                float4 m0v = *(const float4*)mr;
                float4 m1v = *(const float4*)(mr+4);
                vv[0]*=m0v.x; vv[1]*=m0v.y; vv[2]*=m0v.z; vv[3]*=m0v.w;
                vv[4]*=m1v.x; vv[5]*=m1v.y; vv[6]*=m1v.z; vv[7]*=m1v.w;
            } else if (XOP==2){
                #pragma unroll
                for (int j=0;j<8;j++) vv[j] = geluf(vv[j]);
            } else if (XOP==3){
                int o = k0 + kk;
                int bg = b*NGRP + o/CGg;
                float mu=g_mu[bg], rs=g_rstd[bg], ga=g_gamma[o], be=g_beta[o];
                #pragma unroll
                for (int j=0;j<8;j++) vv[j] = geluf((vv[j]-mu)*rs*ga + be);
            }
            #pragma unroll
            for (int j=0;j<4;j++)
                *(unsigned*)&Xs[kk][c0 + j*2] = pack_bf2(vv[j*2], vv[j*2+1]);
        }
        __syncthreads();

        // ---- mma ----
        #pragma unroll
        for (int h=0; h<2; h++){
            int kb = h*16;
            unsigned A[2][4];
            #pragma unroll
            for (int i=0;i<2;i++){
                unsigned addr = smem_u32(&Ws[wm*32 + i*16 + (lane&15)][kb + (lane>>4)*8]);
                asm volatile("ldmatrix.sync.aligned.m8n8.x4.shared.b16 {%0,%1,%2,%3}, [%4];"
                    : "=r"(A[i][0]),"=r"(A[i][1]),"=r"(A[i][2]),"=r"(A[i][3]) : "r"(addr));
            }
            unsigned Bv[4];
            unsigned baddr = smem_u32(&Xs[kb + (lane&7) + 8*((lane>>3)&1)][wp*16 + 8*(lane>>4)]);
            asm volatile("ldmatrix.sync.aligned.m8n8.x4.trans.shared.b16 {%0,%1,%2,%3}, [%4];"
                : "=r"(Bv[0]),"=r"(Bv[1]),"=r"(Bv[2]),"=r"(Bv[3]) : "r"(baddr));
            #pragma unroll
            for (int i=0;i<2;i++)
                #pragma unroll
                for (int j=0;j<2;j++){
                    float* d = acc[i][j];
                    asm volatile("mma.sync.aligned.m16n8k16.row.col.f32.bf16.bf16.f32 "
                        "{%0,%1,%2,%3},{%4,%5,%6,%7},{%8,%9},{%0,%1,%2,%3};"
                        : "+f"(d[0]),"+f"(d[1]),"+f"(d[2]),"+f"(d[3])
                        : "r"(A[i][0]),"r"(A[i][1]),"r"(A[i][2]),"r"(A[i][3]),
                          "r"(Bv[j*2]),"r"(Bv[j*2+1]));
                }
        }
        __syncthreads();
    }

    // ---- epilogue ----
    #pragma unroll
    for (int i=0;i<2;i++){
        int rbase = m0 + wm*32 + i*16 + (lane>>2);
        #pragma unroll
        for (int j=0;j<2;j++){
            int c = p0 + wp*16 + j*8 + (lane&3)*2;
            #pragma unroll
            for (int rr=0; rr<2; rr++){
                int m = rbase + rr*8;
                size_t idx = ((size_t)b*M + m)*HWN + c;
                float v0 = acc[i][j][rr*2+0], v1 = acc[i][j][rr*2+1];
                if (EPI==1){
                    v0 += aux[idx]; v1 += aux[idx+1];
                } else if (EPI==2){
                    float sc = scal[0];
                    size_t mi = (size_t)b*HWN + c;
                    v0 = (v0 - y[idx])  *(1.0f-mask[mi])  *sc;
                    v1 = (v1 - y[idx+1])*(1.0f-mask[mi+1])*sc;
                } else if (EPI==3){
                    v0 *= gelu_grad(aux[idx]); v1 *= gelu_grad(aux[idx+1]);
                } else if (EPI==4){
                    size_t mi = (size_t)b*HWN + c;
                    float cA = g_cA[m], cB = g_cB[m], cm = g_cm[m];
                    v0 = v0*mask[mi]   - aux[idx]   + cA + cB*(y[idx]  -cm);
                    v1 = v1*mask[mi+1] - aux[idx+1] + cA + cB*(y[idx+1]-cm);
                }
                *(float2*)(out+idx) = make_float2(v0, v1);
            }
        }
    }
}

// ============================================================================
// NT GEMM (weight grads): part[z,m,n] = sum_{b, p in z} A[b,m,p] * B'[b,n,p]
// XOPB: 0 none, 3 B'=gelu(GN(h1)) per-channel n
// ============================================================================
template<int XOPB>
__global__ __launch_bounds__(256) void gemm_nt_bf16(
    const float* __restrict__ A, const float* __restrict__ Bm,
    float* __restrict__ part, int Ma, int Nb)
{
    __shared__ __nv_bfloat16 As[64][40];
    __shared__ __nv_bfloat16 Bs[64][40];
    int z  = blockIdx.z;
    int m0 = blockIdx.y*64, n0 = blockIdx.x*64;
    int tid  = threadIdx.x;
    int lane = tid & 31, warp = tid >> 5;
    int wm = warp >> 2, wp = warp & 3;
    float acc[2][2][4] = {};

    int r  = tid >> 2, c0 = (tid & 3)*4;

    for (int b=0; b<BN; b++){
        const float* Ab = A  + ((size_t)b*Ma + m0 + r)*HWN;
        const float* Bb = Bm + ((size_t)b*Nb + n0 + r)*HWN;
        float mu=0.f, rs=0.f, ga=0.f, be=0.f;
        if (XOPB==3){
            int o = n0 + r;
            int bg = b*NGRP + o/CGg;
            mu=g_mu[bg]; rs=g_rstd[bg]; ga=g_gamma[o]; be=g_beta[o];
        }
        for (int blk=0; blk<PBZ; blk++){
            int p0 = (blk*SPLITK + z)*32;
            #pragma unroll
            for (int h=0; h<2; h++){
                float4 av = *(const float4*)(Ab + p0 + c0 + h*16);
                *(unsigned*)&As[r][c0 + h*16]     = pack_bf2(av.x, av.y);
                *(unsigned*)&As[r][c0 + h*16 + 2] = pack_bf2(av.z, av.w);
                float4 bv = *(const float4*)(Bb + p0 + c0 + h*16);
                if (XOPB==3){
                    bv.x = geluf((bv.x-mu)*rs*ga + be);
                    bv.y = geluf((bv.y-mu)*rs*ga + be);
                    bv.z = geluf((bv.z-mu)*rs*ga + be);
                    bv.w = geluf((bv.w-mu)*rs*ga + be);
                }
                *(unsigned*)&Bs[r][c0 + h*16]     = pack_bf2(bv.x, bv.y);
                *(unsigned*)&Bs[r][c0 + h*16 + 2] = pack_bf2(bv.z, bv.w);
            }
            __syncthreads();
            #pragma unroll
            for (int h=0; h<2; h++){
                int kb = h*16;
                unsigned Af[2][4];
                #pragma unroll
                for (int i=0;i<2;i++){
                    unsigned addr = smem_u32(&As[wm*32 + i*16 + (lane&15)][kb + (lane>>4)*8]);
                    asm volatile("ldmatrix.sync.aligned.m8n8.x4.shared.b16 {%0,%1,%2,%3}, [%4];"
                        : "=r"(Af[i][0]),"=r"(Af[i][1]),"=r"(Af[i][2]),"=r"(Af[i][3]) : "r"(addr));
                }
                unsigned Bv[4];
                unsigned baddr = smem_u32(&Bs[wp*16 + (lane&7) + 8*(lane>>4)][kb + 8*((lane>>3)&1)]);
                asm volatile("ldmatrix.sync.aligned.m8n8.x4.shared.b16 {%0,%1,%2,%3}, [%4];"
                    : "=r"(Bv[0]),"=r"(Bv[1]),"=r"(Bv[2]),"=r"(Bv[3]) : "r"(baddr));
                #pragma unroll
                for (int i=0;i<2;i++)
                    #pragma unroll
                    for (int j=0;j<2;j++){
                        float* d = acc[i][j];
                        asm volatile("mma.sync.aligned.m16n8k16.row.col.f32.bf16.bf16.f32 "
                            "{%0,%1,%2,%3},{%4,%5,%6,%7},{%8,%9},{%0,%1,%2,%3};"
                            : "+f"(d[0]),"+f"(d[1]),"+f"(d[2]),"+f"(d[3])
                            : "r"(Af[i][0]),"r"(Af[i][1]),"r"(Af[i][2]),"r"(Af[i][3]),
                              "r"(Bv[j*2]),"r"(Bv[j*2+1]));
                    }
            }
            __syncthreads();
        }
    }
    #pragma unroll
    for (int i=0;i<2;i++){
        int rbase = m0 + wm*32 + i*16 + (lane>>2);
        #pragma unroll
        for (int j=0;j<2;j++){
            int n = n0 + wp*16 + j*8 + (lane&3)*2;
            #pragma unroll
            for (int rr=0; rr<2; rr++){
                int m = rbase + rr*8;
                size_t idx = ((size_t)z*Ma + m)*Nb + n;
                *(float2*)(part+idx) = make_float2(acc[i][j][rr*2], acc[i][j][rr*2+1]);
            }
        }
    }
}

__global__ void reduce_split(const float* __restrict__ part, float* __restrict__ out, int n){
    int i = blockIdx.x*blockDim.x + threadIdx.x;
    if (i < n){
        float s = 0.f;
        for (int z=0; z<SPLITK; z++) s += part[(size_t)z*n + i];
        out[i] = s;
    }
}

// ---------------- GroupNorm fwd stats ----------------
__global__ void gn_stats(const float* __restrict__ h1){
    int bg = blockIdx.x;
    size_t base = (size_t)bg * CGg * HWN;
    const float4* p4 = (const float4*)(h1 + base);
    int n4 = CGg*HWN/4;
    float s=0.f, sq=0.f;
    for (int i=threadIdx.x; i<n4; i+=256){
        float4 v = p4[i];
        s  += v.x+v.y+v.z+v.w;
        sq += v.x*v.x + v.y*v.y + v.z*v.z + v.w*v.w;
    }
    block_reduce2(s, sq);
    if (threadIdx.x==0){
        float n = (float)(CGg*HWN);
        float mean = s/n;
        float var  = sq/n - mean*mean;
        g_mu[bg] = mean;
        g_rstd[bg] = rsqrtf(var + 1e-5f);
    }
}

// per-channel consist stats
__global__ void chan_stats(const float* __restrict__ y, const float* __restrict__ rm,
                           const float* __restrict__ rv){
    int c = blockIdx.x;
    float s=0.f, sq=0.f;
    for (int b=0; b<BN; b++){
        const float4* row = (const float4*)(y + ((size_t)b*CC + c)*HWN);
        for (int i=threadIdx.x; i<HWN/4; i+=256){
            float4 v = row[i];
            s  += v.x+v.y+v.z+v.w;
            sq += v.x*v.x + v.y*v.y + v.z*v.z + v.w*v.w;
        }
    }
    block_reduce2(s, sq);
    if (threadIdx.x==0){
        float n = (float)NTOT;
        float cm = s/n;
        float cv = (sq - n*cm*cm)/(n - 1.0f);
        float rve = rv[c] + 1e-8f;
        g_cm[c] = cm;
        g_cA[c] = 0.1f*2.0f*(cm - rm[c])/(256.0f*n);
        g_cB[c] = 0.1f*4.0f*(cv/rve - 1.0f)/(rve*256.0f*(n - 1.0f));
    }
}

// pass 1: per-(b,o) partial sums of dgn and dgn*hat (no writes of dgn)
__global__ void dgn_stats(const float* __restrict__ h1, const float* __restrict__ dg){
    int o = blockIdx.x, b = blockIdx.y;
    int bg = b*NGRP + o/CGg;
    float mu=g_mu[bg], rs=g_rstd[bg], ga=g_gamma[o], be=g_beta[o];
    size_t base = ((size_t)b*HIDN + o)*HWN;
    const float4* h4 = (const float4*)(h1 + base);
    const float4* d4 = (const float4*)(dg + base);
    float r0=0.f, r1=0.f;
    for (int i=threadIdx.x; i<HWN/4; i+=256){
        float4 h = h4[i];
        float4 d = d4[i];
        float hat, dd;
        hat=(h.x-mu)*rs; dd=d.x*gelu_grad(hat*ga+be); r0+=dd; r1+=dd*hat;
        hat=(h.y-mu)*rs; dd=d.y*gelu_grad(hat*ga+be); r0+=dd; r1+=dd*hat;
        hat=(h.z-mu)*rs; dd=d.z*gelu_grad(hat*ga+be); r0+=dd; r1+=dd*hat;
        hat=(h.w-mu)*rs; dd=d.w*gelu_grad(hat*ga+be); r0+=dd; r1+=dd*hat;
    }
    block_reduce2(r0, r1);
    if (threadIdx.x==0){
        g_part[(b*HIDN+o)*2+0] = r0;
        g_part[(b*HIDN+o)*2+1] = r1;
    }
}

__global__ void reduce_part(){
    int t = threadIdx.x;  // 512
    float db=0.f, dga=0.f;
    for (int b=0;b<BN;b++){
        db  += g_part[(b*HIDN+t)*2+0];
        dga += g_part[(b*HIDN+t)*2+1];
    }
    g_dbeta[t]=db; g_dgamma[t]=dga;
    if (t < BN*NGRP){
        int b=t/NGRP, g=t%NGRP;
        float s1=0.f, s2=0.f;
        for (int j=0;j<CGg;j++){
            int o=g*CGg+j;
            float ga=g_gamma[o];
            s1 += ga*g_part[(b*HIDN+o)*2+0];
            s2 += ga*g_part[(b*HIDN+o)*2+1];
        }
        float inv = 1.0f/(float)(CGg*HWN);
        g_s1[t]=s1*inv; g_s2[t]=s2*inv;
    }
}

// pass 2: dh1 = rstd*(dgn*gamma - s1 - hat*s2), recomputing dgn (in-place over dg)
__global__ void dh1_kernel(const float* __restrict__ h1, float* __restrict__ dg){
    size_t i4 = (size_t)blockIdx.x*blockDim.x + threadIdx.x;
    size_t i  = i4*4;
    int po = (int)(i / HWN);
    int o  = po % HIDN;
    int bg = (po / HIDN)*NGRP + o/CGg;
    float mu=g_mu[bg], rs=g_rstd[bg], ga=g_gamma[o], be=g_beta[o];
    float s1=g_s1[bg], s2=g_s2[bg];
    float4 h = ((const float4*)h1)[i4];
    float4 d = ((float4*)dg)[i4];
    float hat, dd;
    hat=(h.x-mu)*rs; dd=d.x*gelu_grad(hat*ga+be); d.x = rs*(dd*ga - s1 - hat*s2);
    hat=(h.y-mu)*rs; dd=d.y*gelu_grad(hat*ga+be); d.y = rs*(dd*ga - s1 - hat*s2);
    hat=(h.z-mu)*rs; dd=d.z*gelu_grad(hat*ga+be); d.z = rs*(dd*ga - s1 - hat*s2);
    hat=(h.w-mu)*rs; dd=d.w*gelu_grad(hat*ga+be); d.w = rs*(dd*ga - s1 - hat*s2);
    ((float4*)dg)[i4] = d;
}

__global__ void update_params(){
    int i = blockIdx.x*blockDim.x + threadIdx.x;
    if (i < HIDN*CC) g_w1[i] -= LRc*g_dW1[i];
    if (i < CC*HIDN) g_w2[i] -= LRc*g_dW2[i];
    if (i < HIDN){ g_gamma[i] -= LRc*g_dgamma[i]; g_beta[i] -= LRc*g_dbeta[i]; }
}

// ---------------- gate path (param-independent) ----------------
__global__ void pooled_kernel(const float* __restrict__ x){
    int c = blockIdx.x, b = blockIdx.y;
    const float4* row = (const float4*)(x + ((size_t)b*CC + c)*HWN);
    float s=0.f, d=0.f;
    for (int i=threadIdx.x; i<HWN/4; i+=256){
        float4 v = row[i];
        s += v.x+v.y+v.z+v.w;
    }
    block_reduce2(s, d);
    if (threadIdx.x==0) g_pooled[b*CC+c] = s/(float)HWN;
}

__global__ void gate_kernel(const float* __restrict__ gw1, const float* __restrict__ gb1,
                            const float* __restrict__ gw2, const float* __restrict__ gb2){
    __shared__ float gh[BN*CU];
    int t = threadIdx.x;  // 256
    for (int j=t; j<BN*CU; j+=256){
        int b=j/CU, u=j%CU;
        float s = gb1[u];
        const float* pr = &g_pooled[b*CC];
        const float* wr = &gw1[u*CC];
        for (int c=0;c<CC;c++) s += pr[c]*wr[c];
        gh[j] = geluf(s);
    }
    __syncthreads();
    if (t < BN){
        float s = gb2[0];
        for (int u=0;u<CU;u++) s += gh[t*CU+u]*gw2[u];
        g_gate[t] = 1.0f/(1.0f + expf(-s));
    }
}

__global__ void final_out(const float* __restrict__ x, const float* __restrict__ mod,
                          const float* __restrict__ rs, float* __restrict__ out){
    size_t i4 = (size_t)blockIdx.x*blockDim.x + threadIdx.x;
    if (i4 >= (size_t)BN*CC*HWN/4) return;
    int b = (int)(i4 / ((size_t)CC*HWN/4));
    float sc = rs[0]*g_gate[b];
    float4 xv = ((const float4*)x)[i4];
    float4 mv = ((const float4*)mod)[i4];
    xv.x += sc*mv.x; xv.y += sc*mv.y; xv.z += sc*mv.z; xv.w += sc*mv.w;
    ((float4*)out)[i4] = xv;
}

// ---------------- host orchestration ----------------
extern "C" void kernel_launch(void* const* d_in, const int* in_sizes, int n_in,
                              void* d_out, int out_size){
    const float* x        = (const float*)d_in[0];
    const float* conv1_w  = (const float*)d_in[1];
    const float* gn_gammaI= (const float*)d_in[2];
    const float* gn_betaI = (const float*)d_in[3];
    const float* conv2_w  = (const float*)d_in[4];
    const float* rw1      = (const float*)d_in[5];
    const float* rw2      = (const float*)d_in[6];
    const float* gw1      = (const float*)d_in[7];
    const float* gb1      = (const float*)d_in[8];
    const float* gw2      = (const float*)d_in[9];
    const float* gb2      = (const float*)d_in[10];
    const float* rscale   = (const float*)d_in[11];
    const float* rm       = (const float*)d_in[12];
    const float* rv       = (const float*)d_in[13];
    const void*  masks    = d_in[14];

    void* p;
    #define SYMF(sym) (cudaGetSymbolAddress(&p, sym), (float*)p)
    float* pw1    = SYMF(g_w1);
    float* pw2    = SYMF(g_w2);
    float* ph1    = SYMF(g_h1);
    float* pdg    = SYMF(g_dg);
    float* py     = SYMF(g_y);
    float* pdrec  = SYMF(g_drec);
    float* pdy    = SYMF(g_dy);
    float* ppre   = SYMF(g_pre);
    float* pdpre  = SYMF(g_dpre);
    float* psplit = SYMF(g_split);
    float* pdW1   = SYMF(g_dW1);
    float* pdW2   = SYMF(g_dW2);
    float* pmaskf = SYMF(g_maskf);
    float* pdscale= SYMF(g_dscale);
    #undef SYMF

    // ---- init ----
    reset_copy<<<512,256>>>(conv1_w, gn_gammaI, gn_betaI, conv2_w);
    mask_detect<<<32,256>>>((const unsigned int*)masks);
    mask_convert<<<98,1024>>>(masks);
    inv_scale_kernel<<<2,256>>>();
    pooled_kernel<<<dim3(CC,BN),256>>>(x);
    gate_kernel<<<1,256>>>(gw1, gb1, gw2, gb2);

    // ---- 2 inner TTT steps ----
    for (int s=0; s<2; s++){
        const float* mk = pmaskf + (size_t)s*NTOT;
        const float* sc = pdscale + s;

        // forward
        gemm_bf16<0,0,false><<<dim3(49,8,BN),256>>>(pw1, x,    ph1,  512,256, nullptr,nullptr,nullptr,nullptr);
        gn_stats<<<128,256>>>(ph1);
        gemm_bf16<3,1,false><<<dim3(49,4,BN),256>>>(pw2, ph1,  py,   256,512, nullptr, x,     nullptr,nullptr);  // y = w2@gelu(gn(h1)) + x
        gemm_bf16<1,0,false><<<dim3(49,1,BN),256>>>(rw1, py,   ppre,  64,256, mk,      nullptr,nullptr,nullptr); // pre
        gemm_bf16<2,2,false><<<dim3(49,4,BN),256>>>(rw2, ppre, pdrec,256, 64, mk,      nullptr, py,    sc);      // drec
        chan_stats<<<256,256>>>(py, rm, rv);

        // backward through surprise
        gemm_bf16<0,3,true ><<<dim3(49,1,BN),256>>>(rw2, pdrec, pdpre, 64,256, nullptr, ppre,  nullptr,nullptr); // dpre
        gemm_bf16<0,4,true ><<<dim3(49,4,BN),256>>>(rw1, pdpre, pdy,  256, 64, mk,      pdrec, py,     nullptr); // dy

        // backward through modifier
        gemm_bf16<0,0,true ><<<dim3(49,8,BN),256>>>(pw2, pdy,  pdg,   512,256, nullptr,nullptr,nullptr,nullptr); // dg
        dgn_stats<<<dim3(HIDN,BN),256>>>(ph1, pdg);
        reduce_part<<<1,512>>>();
        dh1_kernel<<<25088,256>>>(ph1, pdg);

        gemm_nt_bf16<3><<<dim3(8,4,SPLITK),256>>>(pdy, ph1, psplit, 256,512);   // dW2[c,o] (B = gelu(gn(h1)))
        reduce_split<<<512,256>>>(psplit, pdW2, HIDN*CC);
        gemm_nt_bf16<0><<<dim3(4,8,SPLITK),256>>>(pdg, x,   psplit, 512,256);   // dW1[o,c]
        reduce_split<<<512,256>>>(psplit, pdW1, HIDN*CC);

        update_params<<<512,256>>>();
    }

    // ---- final forward with updated params ----
    gemm_bf16<0,0,false><<<dim3(49,8,BN),256>>>(pw1, x,   ph1, 512,256, nullptr,nullptr,nullptr,nullptr);
    gn_stats<<<128,256>>>(ph1);
    gemm_bf16<3,0,false><<<dim3(49,4,BN),256>>>(pw2, ph1, py,  256,512, nullptr,nullptr,nullptr,nullptr);  // modification

    final_out<<<12544,256>>>(x, py, rscale, (float*)d_out);
    (void)in_sizes; (void)n_in; (void)out_size;
}

// round 3
// speedup vs baseline: 2.4969x; 1.1812x over previous
#include <cuda_runtime.h>
#include <cuda_bf16.h>
#include <cstdint>
#include <math.h>

// ---------------- problem constants ----------------
#define BN    16
#define CC    256
#define HIDN  512
#define NGRP  8
#define CGg   64          // HID / GROUPS
#define HWN   3136
#define CU    64          // C/4 bottleneck
#define NTOT  (BN*HWN)    // 50176
#define LRc   0.01f
#define SPLITK 14
#define PBZ   7           // (HWN/32)/SPLITK = 98/14

typedef __nv_bfloat16 bft;

// ---------------- device scratch (no allocs allowed) ----------------
__device__ float g_w1[HIDN*CC];
__device__ float g_gamma[HIDN];
__device__ float g_beta[HIDN];
__device__ float g_w2[CC*HIDN];

__device__ bft g_h1 [(size_t)BN*HIDN*HWN];
__device__ bft g_dg [(size_t)BN*HIDN*HWN];
__device__ bft g_y  [(size_t)BN*CC*HWN];
__device__ bft g_drec[(size_t)BN*CC*HWN];
__device__ bft g_dy [(size_t)BN*CC*HWN];
__device__ bft g_pre [(size_t)BN*CU*HWN];
__device__ bft g_dpre[(size_t)BN*CU*HWN];
__device__ bft g_xb [(size_t)BN*CC*HWN];
__device__ float g_mod[(size_t)BN*CC*HWN];

__device__ float g_mu[BN*NGRP];
__device__ float g_rstd[BN*NGRP];
__device__ float g_part[BN*HIDN*2];
__device__ float g_s1[BN*NGRP], g_s2[BN*NGRP];
__device__ float g_dgamma[HIDN], g_dbeta[HIDN];
__device__ float g_cm[CC], g_cA[CC], g_cB[CC];
__device__ float g_split[(size_t)SPLITK*HIDN*CC];
__device__ float g_dW1[HIDN*CC], g_dW2[CC*HIDN];
__device__ float g_maskf[2*NTOT];
__device__ float g_dscale[2];
__device__ float g_pooled[BN*CC];
__device__ float g_gate[BN];
__device__ int   g_flagF, g_flagW;

// ---------------- math helpers ----------------
__device__ __forceinline__ float geluf(float x){
    return 0.5f*x*(1.0f + erff(x*0.70710678118654752440f));
}
__device__ __forceinline__ float gelu_grad(float x){
    float cdf = 0.5f*(1.0f + erff(x*0.70710678118654752440f));
    float pdf = 0.3989422804014327f*expf(-0.5f*x*x);
    return cdf + x*pdf;
}
__device__ __forceinline__ void block_reduce2(float& a, float& b){
    __shared__ float sa[256], sb[256];
    int t = threadIdx.x;
    sa[t]=a; sb[t]=b; __syncthreads();
    for (int s=128; s>0; s>>=1){
        if (t<s){ sa[t]+=sa[t+s]; sb[t]+=sb[t+s]; }
        __syncthreads();
    }
    a=sa[0]; b=sb[0];
}
__device__ __forceinline__ unsigned pack_bf2(float a, float b){
    __nv_bfloat162 p = __floats2bfloat162_rn(a, b);
    return *(unsigned*)&p;
}
__device__ __forceinline__ unsigned smem_u32(const void* p){
    return (unsigned)__cvta_generic_to_shared(p);
}
__device__ __forceinline__ void unpack8(uint4 u, float* v){
    __nv_bfloat162 p;
    p=*(__nv_bfloat162*)&u.x; v[0]=__low2float(p); v[1]=__high2float(p);
    p=*(__nv_bfloat162*)&u.y; v[2]=__low2float(p); v[3]=__high2float(p);
    p=*(__nv_bfloat162*)&u.z; v[4]=__low2float(p); v[5]=__high2float(p);
    p=*(__nv_bfloat162*)&u.w; v[6]=__low2float(p); v[7]=__high2float(p);
}
__device__ __forceinline__ uint4 pack8(const float* v){
    uint4 u;
    u.x=pack_bf2(v[0],v[1]); u.y=pack_bf2(v[2],v[3]);
    u.z=pack_bf2(v[4],v[5]); u.w=pack_bf2(v[6],v[7]);
    return u;
}
__device__ __forceinline__ float2 ldbf2(const bft* p){
    __nv_bfloat162 v = *(const __nv_bfloat162*)p;
    return make_float2(__low2float(v), __high2float(v));
}

// ---------------- init / mask handling ----------------
__global__ void reset_copy(const float* __restrict__ w1, const float* __restrict__ gam,
                           const float* __restrict__ bet, const float* __restrict__ w2){
    int i = blockIdx.x*blockDim.x + threadIdx.x;
    if (i==0){ g_flagF=0; g_flagW=0; }
    if (i < HIDN*CC) g_w1[i] = w1[i];
    if (i < CC*HIDN) g_w2[i] = w2[i];
    if (i < HIDN){ g_gamma[i]=gam[i]; g_beta[i]=bet[i]; }
}

__global__ void mask_detect(const unsigned int* __restrict__ mw){
    int f=0, wd=0;
    for (int i = blockIdx.x*blockDim.x + threadIdx.x; i < 25088; i += gridDim.x*blockDim.x){
        unsigned v = mw[i];
        if (v == 0x3F800000u) f = 1;
        else if (v != 0u && v != 1u) wd = 1;
    }
    if (f)  atomicOr(&g_flagF, 1);
    if (wd) atomicOr(&g_flagW, 1);
}

__global__ void mask_convert(const void* __restrict__ mp){
    int mode = g_flagW ? 2 : (g_flagF ? 1 : 0);
    int n = 2*NTOT;
    for (int i = blockIdx.x*blockDim.x + threadIdx.x; i < n; i += gridDim.x*blockDim.x){
        bool v;
        if (mode==0)      v = ((const int*)mp)[i] != 0;
        else if (mode==1) v = ((const float*)mp)[i] != 0.0f;
        else              v = ((const unsigned char*)mp)[i] != 0;
        g_maskf[i] = v ? 1.0f : 0.0f;
    }
}

__global__ void inv_scale_kernel(){
    int s = blockIdx.x;
    float cnt = 0.f, d = 0.f;
    for (int i = threadIdx.x; i < NTOT; i += 256) cnt += 1.0f - g_maskf[s*NTOT + i];
    block_reduce2(cnt, d);
    if (threadIdx.x==0) g_dscale[s] = 2.0f/(cnt*256.0f + 1e-8f);
}

__global__ void convert_x(const float* __restrict__ x, bft* __restrict__ xb){
    size_t i8 = (size_t)blockIdx.x*blockDim.x + threadIdx.x;   // 8 elems each
    size_t i = i8*8;
    float4 a = *(const float4*)(x+i);
    float4 b = *(const float4*)(x+i+4);
    float v[8] = {a.x,a.y,a.z,a.w,b.x,b.y,b.z,b.w};
    *(uint4*)(xb+i) = pack8(v);
}

// ============================================================================
// bf16 tensor-core GEMM: out[b,m,p] = sum_k W(m,k)*X[b,k,p]   (X is bf16)
// XOP: 0 none, 1 X*=mask[b,p], 2 X=gelu(X), 3 X=gelu(GN(X)) per channel k
// EPI: 0 store, 1 +aux, 2 drec=(acc-y)*(1-mask)*scal, 3 *=gelu'(aux),
//      4 dy = acc*mask - aux + cA[m] + cB[m]*(y - cm[m])
// ============================================================================
template<int XOP, int EPI, bool WT, typename TO>
__global__ __launch_bounds__(256) void gemm_bf16(
    const float* __restrict__ W, const bft* __restrict__ X, TO* __restrict__ out,
    int M, int K,
    const float* __restrict__ mask, const bft* __restrict__ aux,
    const bft* __restrict__ y, const float* __restrict__ scal)
{
    __shared__ bft Ws[64][40];
    __shared__ bft Xs[32][72];
    int b  = blockIdx.z;
    int m0 = blockIdx.y*64, p0 = blockIdx.x*64;
    const bft* Xb = X + (size_t)b*K*HWN;
    int tid  = threadIdx.x;
    int lane = tid & 31, warp = tid >> 5;
    int wm = warp >> 2, wp = warp & 3;
    float acc[2][2][4] = {};

    int xk = tid>>3, xc = (tid&7)*8;
    float mv[8];
    if (XOP==1){
        const float* mr = mask + (size_t)b*HWN + p0 + xc;
        float4 a=*(const float4*)mr, b2=*(const float4*)(mr+4);
        mv[0]=a.x;mv[1]=a.y;mv[2]=a.z;mv[3]=a.w;mv[4]=b2.x;mv[5]=b2.y;mv[6]=b2.z;mv[7]=b2.w;
    }

    // prefetch k0 = 0
    float4 wr0, wr1;
    uint4  xreg;
    {
        if (!WT){
            const float* wr = W + (size_t)(m0 + (tid>>2))*K + (tid&3)*4;
            wr0 = *(const float4*)wr; wr1 = *(const float4*)(wr+16);
        } else {
            const float* wr = W + (size_t)(tid&31)*M + m0;
            wr0 = *(const float4*)(wr + (tid>>5)*4);
            wr1 = *(const float4*)(wr + ((tid>>5)+8)*4);
        }
        xreg = *(const uint4*)(Xb + (size_t)xk*HWN + p0 + xc);
    }

    for (int k0 = 0; k0 < K; k0 += 32){
        // ---- store W tile ----
        if (!WT){
            int m = tid>>2, c0 = (tid&3)*4;
            *(unsigned*)&Ws[m][c0]    = pack_bf2(wr0.x, wr0.y);
            *(unsigned*)&Ws[m][c0+2]  = pack_bf2(wr0.z, wr0.w);
            *(unsigned*)&Ws[m][c0+16] = pack_bf2(wr1.x, wr1.y);
            *(unsigned*)&Ws[m][c0+18] = pack_bf2(wr1.z, wr1.w);
        } else {
            int kk = tid&31, cg = tid>>5;
            Ws[cg*4+0][kk]=__float2bfloat16(wr0.x);
            Ws[cg*4+1][kk]=__float2bfloat16(wr0.y);
            Ws[cg*4+2][kk]=__float2bfloat16(wr0.z);
            Ws[cg*4+3][kk]=__float2bfloat16(wr0.w);
            Ws[(cg+8)*4+0][kk]=__float2bfloat16(wr1.x);
            Ws[(cg+8)*4+1][kk]=__float2bfloat16(wr1.y);
            Ws[(cg+8)*4+2][kk]=__float2bfloat16(wr1.z);
            Ws[(cg+8)*4+3][kk]=__float2bfloat16(wr1.w);
        }
        // ---- store X tile (transform) ----
        if (XOP==0){
            *(uint4*)&Xs[xk][xc] = xreg;
        } else {
            float vv[8]; unpack8(xreg, vv);
            if (XOP==1){
                #pragma unroll
                for (int j=0;j<8;j++) vv[j] *= mv[j];
            } else if (XOP==2){
                #pragma unroll
                for (int j=0;j<8;j++) vv[j] = geluf(vv[j]);
            } else {
                int o = k0 + xk;
                int bg = b*NGRP + o/CGg;
                float mu=g_mu[bg], rs=g_rstd[bg], ga=g_gamma[o], be=g_beta[o];
                #pragma unroll
                for (int j=0;j<8;j++) vv[j] = geluf((vv[j]-mu)*rs*ga + be);
            }
            *(uint4*)&Xs[xk][xc] = pack8(vv);
        }
        __syncthreads();

        // ---- prefetch next tile ----
        if (k0 + 32 < K){
            int kn = k0 + 32;
            if (!WT){
                const float* wr = W + (size_t)(m0 + (tid>>2))*K + kn + (tid&3)*4;
                wr0 = *(const float4*)wr; wr1 = *(const float4*)(wr+16);
            } else {
                const float* wr = W + (size_t)(kn + (tid&31))*M + m0;
                wr0 = *(const float4*)(wr + (tid>>5)*4);
                wr1 = *(const float4*)(wr + ((tid>>5)+8)*4);
            }
            xreg = *(const uint4*)(Xb + (size_t)(kn+xk)*HWN + p0 + xc);
        }

        // ---- mma ----
        #pragma unroll
        for (int h=0; h<2; h++){
            int kb = h*16;
            unsigned A[2][4];
            #pragma unroll
            for (int i=0;i<2;i++){
                unsigned addr = smem_u32(&Ws[wm*32 + i*16 + (lane&15)][kb + (lane>>4)*8]);
                asm volatile("ldmatrix.sync.aligned.m8n8.x4.shared.b16 {%0,%1,%2,%3}, [%4];"
                    : "=r"(A[i][0]),"=r"(A[i][1]),"=r"(A[i][2]),"=r"(A[i][3]) : "r"(addr));
            }
            unsigned Bv[4];
            unsigned baddr = smem_u32(&Xs[kb + (lane&7) + 8*((lane>>3)&1)][wp*16 + 8*(lane>>4)]);
            asm volatile("ldmatrix.sync.aligned.m8n8.x4.trans.shared.b16 {%0,%1,%2,%3}, [%4];"
                : "=r"(Bv[0]),"=r"(Bv[1]),"=r"(Bv[2]),"=r"(Bv[3]) : "r"(baddr));
            #pragma unroll
            for (int i=0;i<2;i++)
                #pragma unroll
                for (int j=0;j<2;j++){
                    float* d = acc[i][j];
                    asm volatile("mma.sync.aligned.m16n8k16.row.col.f32.bf16.bf16.f32 "
                        "{%0,%1,%2,%3},{%4,%5,%6,%7},{%8,%9},{%0,%1,%2,%3};"
                        : "+f"(d[0]),"+f"(d[1]),"+f"(d[2]),"+f"(d[3])
                        : "r"(A[i][0]),"r"(A[i][1]),"r"(A[i][2]),"r"(A[i][3]),
                          "r"(Bv[j*2]),"r"(Bv[j*2+1]));
                }
        }
        __syncthreads();
    }

    // ---- epilogue ----
    #pragma unroll
    for (int i=0;i<2;i++){
        int rbase = m0 + wm*32 + i*16 + (lane>>2);
        #pragma unroll
        for (int j=0;j<2;j++){
            int c = p0 + wp*16 + j*8 + (lane&3)*2;
            #pragma unroll
            for (int rr=0; rr<2; rr++){
                int m = rbase + rr*8;
                size_t idx = ((size_t)b*M + m)*HWN + c;
                float v0 = acc[i][j][rr*2+0], v1 = acc[i][j][rr*2+1];
                if (EPI==1){
                    float2 a = ldbf2(aux+idx);
                    v0 += a.x; v1 += a.y;
                } else if (EPI==2){
                    float sc = scal[0];
                    size_t mi = (size_t)b*HWN + c;
                    float2 mk = *(const float2*)(mask+mi);
                    float2 yv = ldbf2(y+idx);
                    v0 = (v0 - yv.x)*(1.0f-mk.x)*sc;
                    v1 = (v1 - yv.y)*(1.0f-mk.y)*sc;
                } else if (EPI==3){
                    float2 a = ldbf2(aux+idx);
                    v0 *= gelu_grad(a.x); v1 *= gelu_grad(a.y);
                } else if (EPI==4){
                    size_t mi = (size_t)b*HWN + c;
                    float2 mk = *(const float2*)(mask+mi);
                    float2 a  = ldbf2(aux+idx);
                    float2 yv = ldbf2(y+idx);
                    float cA = g_cA[m], cB = g_cB[m], cm = g_cm[m];
                    v0 = v0*mk.x - a.x + cA + cB*(yv.x-cm);
                    v1 = v1*mk.y - a.y + cA + cB*(yv.y-cm);
                }
                if (sizeof(TO)==4)
                    *(float2*)((float*)out+idx) = make_float2(v0, v1);
                else
                    *(unsigned*)((bft*)out+idx) = pack_bf2(v0, v1);
            }
        }
    }
}

// ============================================================================
// NT GEMM (weight grads): part[z,m,n] = sum_{b,p in z} A[b,m,p]*B'[b,n,p]
// XOPB: 0 none, 3 B'=gelu(GN(B)) per channel n
// ============================================================================
template<int XOPB>
__global__ __launch_bounds__(256) void gemm_nt_bf16(
    const bft* __restrict__ A, const bft* __restrict__ Bm,
    float* __restrict__ part, int Ma, int Nb)
{
    __shared__ bft As[64][40];
    __shared__ bft Bs[64][40];
    int z  = blockIdx.z;
    int m0 = blockIdx.y*64, n0 = blockIdx.x*64;
    int tid  = threadIdx.x;
    int lane = tid & 31, warp = tid >> 5;
    int wm = warp >> 2, wp = warp & 3;
    float acc[2][2][4] = {};

    int r  = tid >> 2, c0 = (tid & 3)*8;

    #define ADDR_A(it) (A  + ((size_t)((it)/PBZ)*Ma + m0 + r)*HWN + (((it)%PBZ)*SPLITK + z)*32 + c0)
    #define ADDR_B(it) (Bm + ((size_t)((it)/PBZ)*Nb + n0 + r)*HWN + (((it)%PBZ)*SPLITK + z)*32 + c0)

    uint4 areg = *(const uint4*)ADDR_A(0);
    uint4 breg = *(const uint4*)ADDR_B(0);

    const int ITERS = BN*PBZ;
    for (int it=0; it<ITERS; it++){
        *(uint4*)&As[r][c0] = areg;
        if (XOPB==0){
            *(uint4*)&Bs[r][c0] = breg;
        } else {
            int b = it/PBZ;
            int o = n0 + r;
            int bg = b*NGRP + o/CGg;
            float mu=g_mu[bg], rs=g_rstd[bg], ga=g_gamma[o], be=g_beta[o];
            float v[8]; unpack8(breg, v);
            #pragma unroll
            for (int j=0;j<8;j++) v[j] = geluf((v[j]-mu)*rs*ga + be);
            *(uint4*)&Bs[r][c0] = pack8(v);
        }
        __syncthreads();
        if (it+1 < ITERS){
            areg = *(const uint4*)ADDR_A(it+1);
            breg = *(const uint4*)ADDR_B(it+1);
        }
        #pragma unroll
        for (int h=0; h<2; h++){
            int kb = h*16;
            unsigned Af[2][4];
            #pragma unroll
            for (int i=0;i<2;i++){
                unsigned addr = smem_u32(&As[wm*32 + i*16 + (lane&15)][kb + (lane>>4)*8]);
                asm volatile("ldmatrix.sync.aligned.m8n8.x4.shared.b16 {%0,%1,%2,%3}, [%4];"
                    : "=r"(Af[i][0]),"=r"(Af[i][1]),"=r"(Af[i][2]),"=r"(Af[i][3]) : "r"(addr));
            }
            unsigned Bv[4];
            unsigned baddr = smem_u32(&Bs[wp*16 + (lane&7) + 8*(lane>>4)][kb + 8*((lane>>3)&1)]);
            asm volatile("ldmatrix.sync.aligned.m8n8.x4.shared.b16 {%0,%1,%2,%3}, [%4];"
                : "=r"(Bv[0]),"=r"(Bv[1]),"=r"(Bv[2]),"=r"(Bv[3]) : "r"(baddr));
            #pragma unroll
            for (int i=0;i<2;i++)
                #pragma unroll
                for (int j=0;j<2;j++){
                    float* d = acc[i][j];
                    asm volatile("mma.sync.aligned.m16n8k16.row.col.f32.bf16.bf16.f32 "
                        "{%0,%1,%2,%3},{%4,%5,%6,%7},{%8,%9},{%0,%1,%2,%3};"
                        : "+f"(d[0]),"+f"(d[1]),"+f"(d[2]),"+f"(d[3])
                        : "r"(Af[i][0]),"r"(Af[i][1]),"r"(Af[i][2]),"r"(Af[i][3]),
                          "r"(Bv[j*2]),"r"(Bv[j*2+1]));
                }
        }
        __syncthreads();
    }
    #undef ADDR_A
    #undef ADDR_B

    #pragma unroll
    for (int i=0;i<2;i++){
        int rbase = m0 + wm*32 + i*16 + (lane>>2);
        #pragma unroll
        for (int j=0;j<2;j++){
            int n = n0 + wp*16 + j*8 + (lane&3)*2;
            #pragma unroll
            for (int rr=0; rr<2; rr++){
                int m = rbase + rr*8;
                size_t idx = ((size_t)z*Ma + m)*Nb + n;
                *(float2*)(part+idx) = make_float2(acc[i][j][rr*2], acc[i][j][rr*2+1]);
            }
        }
    }
}

__global__ void reduce_split(const float* __restrict__ part, float* __restrict__ out, int n){
    int i = blockIdx.x*blockDim.x + threadIdx.x;
    if (i < n){
        float s = 0.f;
        for (int z=0; z<SPLITK; z++) s += part[(size_t)z*n + i];
        out[i] = s;
    }
}

// ---------------- GroupNorm fwd stats (bf16 input) ----------------
__global__ void gn_stats(const bft* __restrict__ h1){
    int bg = blockIdx.x;
    size_t base = (size_t)bg * CGg * HWN;
    const uint4* p8 = (const uint4*)(h1 + base);
    int n8 = CGg*HWN/8;
    float s=0.f, sq=0.f;
    for (int i=threadIdx.x; i<n8; i+=256){
        float v[8]; unpack8(p8[i], v);
        #pragma unroll
        for (int j=0;j<8;j++){ s += v[j]; sq += v[j]*v[j]; }
    }
    block_reduce2(s, sq);
    if (threadIdx.x==0){
        float n = (float)(CGg*HWN);
        float mean = s/n;
        float var  = sq/n - mean*mean;
        g_mu[bg] = mean;
        g_rstd[bg] = rsqrtf(var + 1e-5f);
    }
}

// per-channel consist stats (bf16 y)
__global__ void chan_stats(const bft* __restrict__ y, const float* __restrict__ rm,
                           const float* __restrict__ rv){
    int c = blockIdx.x;
    float s=0.f, sq=0.f;
    for (int b=0; b<BN; b++){
        const uint4* row = (const uint4*)(y + ((size_t)b*CC + c)*HWN);
        for (int i=threadIdx.x; i<HWN/8; i+=256){
            float v[8]; unpack8(row[i], v);
            #pragma unroll
            for (int j=0;j<8;j++){ s += v[j]; sq += v[j]*v[j]; }
        }
    }
    block_reduce2(s, sq);
    if (threadIdx.x==0){
        float n = (float)NTOT;
        float cm = s/n;
        float cv = (sq - n*cm*cm)/(n - 1.0f);
        float rve = rv[c] + 1e-8f;
        g_cm[c] = cm;
        g_cA[c] = 0.1f*2.0f*(cm - rm[c])/(256.0f*n);
        g_cB[c] = 0.1f*4.0f*(cv/rve - 1.0f)/(rve*256.0f*(n - 1.0f));
    }
}

// pass 1: per-(b,o) partial sums of dgn and dgn*hat
__global__ void dgn_stats(const bft* __restrict__ h1, const bft* __restrict__ dg){
    int o = blockIdx.x, b = blockIdx.y;
    int bg = b*NGRP + o/CGg;
    float mu=g_mu[bg], rs=g_rstd[bg], ga=g_gamma[o], be=g_beta[o];
    size_t base = ((size_t)b*HIDN + o)*HWN;
    const uint4* h8 = (const uint4*)(h1 + base);
    const uint4* d8 = (const uint4*)(dg + base);
    float r0=0.f, r1=0.f;
    for (int i=threadIdx.x; i<HWN/8; i+=256){
        float hv[8], dv[8];
        unpack8(h8[i], hv); unpack8(d8[i], dv);
        #pragma unroll
        for (int j=0;j<8;j++){
            float hat = (hv[j]-mu)*rs;
            float dd  = dv[j]*gelu_grad(hat*ga+be);
            r0 += dd; r1 += dd*hat;
        }
    }
    block_reduce2(r0, r1);
    if (threadIdx.x==0){
        g_part[(b*HIDN+o)*2+0] = r0;
        g_part[(b*HIDN+o)*2+1] = r1;
    }
}

__global__ void reduce_part(){
    int t = threadIdx.x;  // 512
    float db=0.f, dga=0.f;
    for (int b=0;b<BN;b++){
        db  += g_part[(b*HIDN+t)*2+0];
        dga += g_part[(b*HIDN+t)*2+1];
    }
    g_dbeta[t]=db; g_dgamma[t]=dga;
    if (t < BN*NGRP){
        int b=t/NGRP, g=t%NGRP;
        float s1=0.f, s2=0.f;
        for (int j=0;j<CGg;j++){
            int o=g*CGg+j;
            float ga=g_gamma[o];
            s1 += ga*g_part[(b*HIDN+o)*2+0];
            s2 += ga*g_part[(b*HIDN+o)*2+1];
        }
        float inv = 1.0f/(float)(CGg*HWN);
        g_s1[t]=s1*inv; g_s2[t]=s2*inv;
    }
}

// pass 2: dh1 = rstd*(dgn*gamma - s1 - hat*s2), recomputing dgn (in-place)
__global__ void dh1_kernel(const bft* __restrict__ h1, bft* __restrict__ dg){
    size_t i8 = (size_t)blockIdx.x*blockDim.x + threadIdx.x;
    size_t i  = i8*8;
    int po = (int)(i / HWN);
    int o  = po % HIDN;
    int bg = (po / HIDN)*NGRP + o/CGg;
    float mu=g_mu[bg], rs=g_rstd[bg], ga=g_gamma[o], be=g_beta[o];
    float s1=g_s1[bg], s2=g_s2[bg];
    float hv[8], dv[8];
    unpack8(*(const uint4*)(h1+i), hv);
    unpack8(*(const uint4*)(dg+i), dv);
    #pragma unroll
    for (int j=0;j<8;j++){
        float hat = (hv[j]-mu)*rs;
        float dd  = dv[j]*gelu_grad(hat*ga+be);
        dv[j] = rs*(dd*ga - s1 - hat*s2);
    }
    *(uint4*)(dg+i) = pack8(dv);
}

__global__ void update_params(){
    int i = blockIdx.x*blockDim.x + threadIdx.x;
    if (i < HIDN*CC) g_w1[i] -= LRc*g_dW1[i];
    if (i < CC*HIDN) g_w2[i] -= LRc*g_dW2[i];
    if (i < HIDN){ g_gamma[i] -= LRc*g_dgamma[i]; g_beta[i] -= LRc*g_dbeta[i]; }
}

// ---------------- gate path ----------------
__global__ void pooled_kernel(const float* __restrict__ x){
    int c = blockIdx.x, b = blockIdx.y;
    const float4* row = (const float4*)(x + ((size_t)b*CC + c)*HWN);
    float s=0.f, d=0.f;
    for (int i=threadIdx.x; i<HWN/4; i+=256){
        float4 v = row[i];
        s += v.x+v.y+v.z+v.w;
    }
    block_reduce2(s, d);
    if (threadIdx.x==0) g_pooled[b*CC+c] = s/(float)HWN;
}

__global__ void gate_kernel(const float* __restrict__ gw1, const float* __restrict__ gb1,
                            const float* __restrict__ gw2, const float* __restrict__ gb2){
    __shared__ float gh[BN*CU];
    int t = threadIdx.x;
    for (int j=t; j<BN*CU; j+=256){
        int b=j/CU, u=j%CU;
        float s = gb1[u];
        const float* pr = &g_pooled[b*CC];
        const float* wr = &gw1[u*CC];
        for (int c=0;c<CC;c++) s += pr[c]*wr[c];
        gh[j] = geluf(s);
    }
    __syncthreads();
    if (t < BN){
        float s = gb2[0];
        for (int u=0;u<CU;u++) s += gh[t*CU+u]*gw2[u];
        g_gate[t] = 1.0f/(1.0f + expf(-s));
    }
}

__global__ void final_out(const float* __restrict__ x, const float* __restrict__ mod,
                          const float* __restrict__ rs, float* __restrict__ out){
    size_t i4 = (size_t)blockIdx.x*blockDim.x + threadIdx.x;
    if (i4 >= (size_t)BN*CC*HWN/4) return;
    int b = (int)(i4 / ((size_t)CC*HWN/4));
    float sc = rs[0]*g_gate[b];
    float4 xv = ((const float4*)x)[i4];
    float4 mv = ((const float4*)mod)[i4];
    xv.x += sc*mv.x; xv.y += sc*mv.y; xv.z += sc*mv.z; xv.w += sc*mv.w;
    ((float4*)out)[i4] = xv;
}

// ---------------- host orchestration ----------------
extern "C" void kernel_launch(void* const* d_in, const int* in_sizes, int n_in,
                              void* d_out, int out_size){
    const float* x        = (const float*)d_in[0];
    const float* conv1_w  = (const float*)d_in[1];
    const float* gn_gammaI= (const float*)d_in[2];
    const float* gn_betaI = (const float*)d_in[3];
    const float* conv2_w  = (const float*)d_in[4];
    const float* rw1      = (const float*)d_in[5];
    const float* rw2      = (const float*)d_in[6];
    const float* gw1      = (const float*)d_in[7];
    const float* gb1      = (const float*)d_in[8];
    const float* gw2      = (const float*)d_in[9];
    const float* gb2      = (const float*)d_in[10];
    const float* rscale   = (const float*)d_in[11];
    const float* rm       = (const float*)d_in[12];
    const float* rv       = (const float*)d_in[13];
    const void*  masks    = d_in[14];

    void* p;
    #define SYMF(sym) (cudaGetSymbolAddress(&p, sym), (float*)p)
    #define SYMB(sym) (cudaGetSymbolAddress(&p, sym), (bft*)p)
    float* pw1    = SYMF(g_w1);
    float* pw2    = SYMF(g_w2);
    bft*   ph1    = SYMB(g_h1);
    bft*   pdg    = SYMB(g_dg);
    bft*   py     = SYMB(g_y);
    bft*   pdrec  = SYMB(g_drec);
    bft*   pdy    = SYMB(g_dy);
    bft*   ppre   = SYMB(g_pre);
    bft*   pdpre  = SYMB(g_dpre);
    bft*   pxb    = SYMB(g_xb);
    float* pmod   = SYMF(g_mod);
    float* psplit = SYMF(g_split);
    float* pdW1   = SYMF(g_dW1);
    float* pdW2   = SYMF(g_dW2);
    float* pmaskf = SYMF(g_maskf);
    float* pdscale= SYMF(g_dscale);
    #undef SYMF
    #undef SYMB

    // ---- init ----
    reset_copy<<<512,256>>>(conv1_w, gn_gammaI, gn_betaI, conv2_w);
    mask_detect<<<32,256>>>((const unsigned int*)masks);
    mask_convert<<<98,1024>>>(masks);
    inv_scale_kernel<<<2,256>>>();
    convert_x<<<6272,256>>>(x, pxb);
    pooled_kernel<<<dim3(CC,BN),256>>>(x);
    gate_kernel<<<1,256>>>(gw1, gb1, gw2, gb2);

    // ---- 2 inner TTT steps ----
    for (int s=0; s<2; s++){
        const float* mk = pmaskf + (size_t)s*NTOT;
        const float* sc = pdscale + s;

        // forward
        gemm_bf16<0,0,false,bft><<<dim3(49,8,BN),256>>>(pw1, pxb,  ph1,  512,256, nullptr,nullptr,nullptr,nullptr);
        gn_stats<<<128,256>>>(ph1);
        gemm_bf16<3,1,false,bft><<<dim3(49,4,BN),256>>>(pw2, ph1,  py,   256,512, nullptr, pxb,   nullptr,nullptr);
        gemm_bf16<1,0,false,bft><<<dim3(49,1,BN),256>>>(rw1, py,   ppre,  64,256, mk,      nullptr,nullptr,nullptr);
        gemm_bf16<2,2,false,bft><<<dim3(49,4,BN),256>>>(rw2, ppre, pdrec,256, 64, mk,      nullptr, py,    sc);
        chan_stats<<<256,256>>>(py, rm, rv);

        // backward through surprise
        gemm_bf16<0,3,true,bft><<<dim3(49,1,BN),256>>>(rw2, pdrec, pdpre, 64,256, nullptr, ppre,  nullptr,nullptr);
        gemm_bf16<0,4,true,bft><<<dim3(49,4,BN),256>>>(rw1, pdpre, pdy,  256, 64, mk,      pdrec, py,     nullptr);

        // backward through modifier
        gemm_bf16<0,0,true,bft><<<dim3(49,8,BN),256>>>(pw2, pdy,  pdg,   512,256, nullptr,nullptr,nullptr,nullptr);
        dgn_stats<<<dim3(HIDN,BN),256>>>(ph1, pdg);
        reduce_part<<<1,512>>>();
        dh1_kernel<<<12544,256>>>(ph1, pdg);

        gemm_nt_bf16<3><<<dim3(8,4,SPLITK),256>>>(pdy, ph1, psplit, 256,512);
        reduce_split<<<512,256>>>(psplit, pdW2, HIDN*CC);
        gemm_nt_bf16<0><<<dim3(4,8,SPLITK),256>>>(pdg, pxb, psplit, 512,256);
        reduce_split<<<512,256>>>(psplit, pdW1, HIDN*CC);

        update_params<<<512,256>>>();
    }

    // ---- final forward with updated params ----
    gemm_bf16<0,0,false,bft><<<dim3(49,8,BN),256>>>(pw1, pxb, ph1, 512,256, nullptr,nullptr,nullptr,nullptr);
    gn_stats<<<128,256>>>(ph1);
    gemm_bf16<3,0,false,float><<<dim3(49,4,BN),256>>>(pw2, ph1, pmod, 256,512, nullptr,nullptr,nullptr,nullptr);

    final_out<<<12544,256>>>(x, pmod, rscale, (float*)d_out);
    (void)in_sizes; (void)n_in; (void)out_size;
}